// round 12
// baseline (speedup 1.0000x reference)
#include <cuda_runtime.h>
#include <cuda_bf16.h>
#include <cstdint>
#include <math.h>

using u32 = unsigned int;

// Problem constants
#define BB 4
#define TT 2048
#define DD 2048
#define HH 16
#define HDIM 128

// Scratch (allocation-free rule: __device__ globals)
__device__ float g_qkv[(size_t)BB * TT * 3 * DD];   // (B*T, 3D)
__device__ float g_y[(size_t)BB * TT * DD];         // (B*T, D)
__device__ float g_xr[(size_t)BB * TT * DD];        // tf32-rounded x
__device__ float g_wq[(size_t)3 * DD * DD];         // tf32-rounded w_qkv
__device__ float g_wo[(size_t)DD * DD];             // tf32-rounded w_o
// bf16 K/V planes: [(b*16+h)][t][128] bf16 (row = 256B), as u32
__device__ u32 g_kh[(size_t)64 * 2048 * 64];
__device__ u32 g_kl[(size_t)64 * 2048 * 64];
__device__ u32 g_vh[(size_t)64 * 2048 * 64];
__device__ u32 g_vl[(size_t)64 * 2048 * 64];

__device__ __forceinline__ u32 smem_u32(const void* p) {
    u32 a;
    asm("{ .reg .u64 t; cvta.to.shared.u64 t, %1; cvt.u32.u64 %0, t; }"
        : "=r"(a) : "l"(p));
    return a;
}

__device__ __forceinline__ u32 f2tf32(float f) {
    u32 u;
    asm("cvt.rna.tf32.f32 %0, %1;" : "=r"(u) : "f"(f));
    return u;
}

__device__ __forceinline__ u32 packbf(float lo, float hi) {
    u32 r;
    asm("cvt.rn.bf16x2.f32 %0, %1, %2;" : "=r"(r) : "f"(hi), "f"(lo));
    return r;
}

__device__ __forceinline__ void bsplit(float v, float& hi, float& lo) {
    __nv_bfloat16 h = __float2bfloat16_rn(v);
    hi = __bfloat162float(h);
    lo = v - hi;
}

__device__ __forceinline__ void split8_u4(const float* v, uint4& hc, uint4& lc) {
    float h[8], l[8];
#pragma unroll
    for (int i = 0; i < 8; i++) bsplit(v[i], h[i], l[i]);
    hc = make_uint4(packbf(h[0], h[1]), packbf(h[2], h[3]),
                    packbf(h[4], h[5]), packbf(h[6], h[7]));
    lc = make_uint4(packbf(l[0], l[1]), packbf(l[2], l[3]),
                    packbf(l[4], l[5]), packbf(l[6], l[7]));
}

// ---------------------------------------------------------------------------
// Pre-round pass: dst[i] = tf32_rna(src[i])
// ---------------------------------------------------------------------------
__global__ void round_tf32(const float* __restrict__ src, float* __restrict__ dst,
                           int n4) {
    int i = blockIdx.x * blockDim.x + threadIdx.x;
    if (i < n4) {
        float4 v = ((const float4*)src)[i];
        ((float4*)dst)[i] = make_float4(
            __uint_as_float(f2tf32(v.x)), __uint_as_float(f2tf32(v.y)),
            __uint_as_float(f2tf32(v.z)), __uint_as_float(f2tf32(v.w)));
    }
}

// ---------------------------------------------------------------------------
// K/V split prepass (unchanged from R11, known-pass)
// ---------------------------------------------------------------------------
__global__ void split_kv(const float* __restrict__ qkv,
                         u32* __restrict__ kh, u32* __restrict__ kl,
                         u32* __restrict__ vh, u32* __restrict__ vl) {
    int t = blockIdx.x * blockDim.x + threadIdx.x;
    if (t >= 64 * 2048 * 16) return;
    int c8 = t & 15;
    int tok = (t >> 4) & 2047;
    int bh = t >> 15;
    int b = bh >> 4, h = bh & 15;
    const float* src = qkv + ((size_t)(b * 2048 + tok) * 6144) + 2048 + h * 128
                     + c8 * 8;
    float kv[8], vv[8];
    *(float4*)&kv[0] = *(const float4*)src;
    *(float4*)&kv[4] = *(const float4*)(src + 4);
    *(float4*)&vv[0] = *(const float4*)(src + 2048);
    *(float4*)&vv[4] = *(const float4*)(src + 2052);
    size_t di = ((size_t)bh * 2048 + tok) * 64 + c8 * 4;   // u32 index
    uint4 hc, lc;
    split8_u4(kv, hc, lc);
    *(uint4*)(kh + di) = hc;
    *(uint4*)(kl + di) = lc;
    split8_u4(vv, hc, lc);
    *(uint4*)(vh + di) = hc;
    *(uint4*)(vl + di) = lc;
}

// ---------------------------------------------------------------------------
// TF32 GEMM v3 (unchanged from R10, known-pass)
// ---------------------------------------------------------------------------
#define GST 36
#define A_BYTES (128 * GST * 4)
#define STAGE_B (2 * A_BYTES)
#define GEMM_SMEM3 (3 * STAGE_B)
#define RCHUNK (32 * GST * 4)

__device__ __forceinline__ void mma_tf32(float* d, const u32* a, const u32* b) {
    asm volatile(
        "mma.sync.aligned.m16n8k8.row.col.f32.tf32.tf32.f32 "
        "{%0,%1,%2,%3}, {%4,%5,%6,%7}, {%8,%9}, {%0,%1,%2,%3};"
        : "+f"(d[0]), "+f"(d[1]), "+f"(d[2]), "+f"(d[3])
        : "r"(a[0]), "r"(a[1]), "r"(a[2]), "r"(a[3]), "r"(b[0]), "r"(b[1]));
}

__device__ __forceinline__ void ldmx4(u32* r, u32 addr) {
    asm volatile("ldmatrix.sync.aligned.m8n8.x4.shared.b16 {%0,%1,%2,%3}, [%4];"
                 : "=r"(r[0]), "=r"(r[1]), "=r"(r[2]), "=r"(r[3]) : "r"(addr));
}

__device__ __forceinline__ void cp16(u32 dst, const void* src) {
    asm volatile("cp.async.cg.shared.global [%0], [%1], 16;"
                 :: "r"(dst), "l"(src) : "memory");
}

__global__ __launch_bounds__(256, 2)
void gemm_nt_tf32p(const float* __restrict__ A, const float* __restrict__ B,
                   float* __restrict__ C, int M, int N, int K) {
    extern __shared__ char sm3[];
    const u32 sbase = smem_u32(sm3);
    const int tid = threadIdx.x;
    const int warp = tid >> 5, lane = tid & 31;
    const int wm = warp >> 1, wn = warp & 1;
    const int fr = lane >> 2, fc = lane & 3;
    const int row0 = blockIdx.y * 128, col0 = blockIdx.x * 128;

    const int lrow = tid >> 3, lcc = tid & 7;
    const u32 so0 = (u32)(lrow * GST + lcc * 4) * 4;
    const float* ga0 = A + (size_t)(row0 + lrow) * K + lcc * 4;
    const float* gb0 = B + (size_t)(col0 + lrow) * K + lcc * 4;
    const size_t rstep = (size_t)32 * K;

    const int gl = lane >> 3, lr8 = lane & 7;
    const u32 afrag = (u32)((wm * 32 + (gl & 1) * 8 + lr8) * GST + (gl >> 1) * 4) * 4;
    const u32 bfrag = A_BYTES +
        (u32)((wn * 64 + (gl >> 1) * 8 + lr8) * GST + (gl & 1) * 4) * 4;

    float acc[2][8][4];
#pragma unroll
    for (int mf = 0; mf < 2; mf++)
#pragma unroll
        for (int g = 0; g < 8; g++)
#pragma unroll
            for (int i = 0; i < 4; i++) acc[mf][g][i] = 0.f;

    const int nslabs = K / 32;

#define ISSUE(slab)                                                          \
    {                                                                        \
        const int st_ = (slab) % 3;                                          \
        const int k0_ = (slab) * 32;                                         \
        const u32 sb_ = sbase + st_ * STAGE_B;                               \
        _Pragma("unroll")                                                    \
        for (int s_ = 0; s_ < 4; s_++) {                                     \
            cp16(sb_ + so0 + RCHUNK * s_, ga0 + rstep * s_ + k0_);           \
            cp16(sb_ + A_BYTES + so0 + RCHUNK * s_, gb0 + rstep * s_ + k0_); \
        }                                                                    \
        asm volatile("cp.async.commit_group;" ::: "memory");                 \
    }

    ISSUE(0);
    ISSUE(1);

#pragma unroll 1
    for (int c = 0; c < nslabs; c++) {
        if (c + 1 < nslabs)
            asm volatile("cp.async.wait_group 1;" ::: "memory");
        else
            asm volatile("cp.async.wait_group 0;" ::: "memory");
        __syncthreads();
        if (c + 2 < nslabs) ISSUE(c + 2);

        const u32 sb = sbase + (c % 3) * STAGE_B;
#pragma unroll
        for (int ks = 0; ks < 32; ks += 8) {
            u32 a[2][4], b[8][2];
            ldmx4(a[0], sb + afrag + ks * 4);
            ldmx4(a[1], sb + afrag + 16 * GST * 4 + ks * 4);
#pragma unroll
            for (int j = 0; j < 4; j++) {
                u32 r[4];
                ldmx4(r, sb + bfrag + j * 16 * GST * 4 + ks * 4);
                b[2 * j][0] = r[0]; b[2 * j][1] = r[1];
                b[2 * j + 1][0] = r[2]; b[2 * j + 1][1] = r[3];
            }
#pragma unroll
            for (int mf = 0; mf < 2; mf++)
#pragma unroll
                for (int g = 0; g < 8; g++)
                    mma_tf32(acc[mf][g], a[mf], b[g]);
        }
    }

#pragma unroll
    for (int mf = 0; mf < 2; mf++) {
#pragma unroll
        for (int g = 0; g < 8; g++) {
            int rr = row0 + wm * 32 + mf * 16 + fr;
            int cc = col0 + wn * 64 + g * 8 + 2 * fc;
            *(float2*)(C + (size_t)rr * N + cc) =
                make_float2(acc[mf][g][0], acc[mf][g][1]);
            *(float2*)(C + (size_t)(rr + 8) * N + cc) =
                make_float2(acc[mf][g][2], acc[mf][g][3]);
        }
    }
#undef ISSUE
}

// ===========================================================================
// Flash attention v5: 128 threads (4 warps x 16 q-rows = 64 rows/CTA),
// kv chunks of 32, 2-stage cp.async, 2 CTAs/SM for softmax/mma overlap.
// ===========================================================================
#define APL2 8192                       // bytes per plane per stage (32 rows)
#define ASTAGE2 (4 * APL2)              // 32768
#define ABIAS2 (2 * ASTAGE2)            // 65536
#define ATTN4_SMEM (2 * ASTAGE2 + 2048 * 4)

__device__ __forceinline__ void mma16816(float* c, const u32* a, const u32* b) {
    asm volatile(
        "mma.sync.aligned.m16n8k16.row.col.f32.bf16.bf16.f32 "
        "{%0,%1,%2,%3}, {%4,%5,%6,%7}, {%8,%9}, {%0,%1,%2,%3};"
        : "+f"(c[0]), "+f"(c[1]), "+f"(c[2]), "+f"(c[3])
        : "r"(a[0]), "r"(a[1]), "r"(a[2]), "r"(a[3]), "r"(b[0]), "r"(b[1]));
}

__device__ __forceinline__ void ldsm_x2(u32& r0, u32& r1, u32 addr) {
    asm volatile("ldmatrix.sync.aligned.m8n8.x2.shared.b16 {%0,%1}, [%2];"
                 : "=r"(r0), "=r"(r1) : "r"(addr));
}

__device__ __forceinline__ void ldsm_x2_t(u32& r0, u32& r1, u32 addr) {
    asm volatile("ldmatrix.sync.aligned.m8n8.x2.trans.shared.b16 {%0,%1}, [%2];"
                 : "=r"(r0), "=r"(r1) : "r"(addr));
}

__device__ __forceinline__ float exp2_fast(float t) {
    t = fmaxf(t, -126.f);
    float k = rintf(t);
    float f = t - k;
    float u = f * 0.69314718056f;
    float p = 0.0013888889f;
    p = fmaf(p, u, 0.008333334f);
    p = fmaf(p, u, 0.041666668f);
    p = fmaf(p, u, 0.16666667f);
    p = fmaf(p, u, 0.5f);
    p = fmaf(p, u, 1.0f);
    p = fmaf(p, u, 1.0f);
    return __int_as_float(((int)k + 127) << 23) * p;
}

__device__ __forceinline__ void pack_split2(float a, float b, u32& hp, u32& lp) {
    float ha, la, hb, lb;
    bsplit(a, ha, la);
    bsplit(b, hb, lb);
    hp = packbf(ha, hb);
    lp = packbf(la, lb);
}

__global__ __launch_bounds__(128, 2)
void attn_mma(const float* __restrict__ qkv, const int* __restrict__ mask,
              const u32* __restrict__ kh, const u32* __restrict__ kl,
              const u32* __restrict__ vh, const u32* __restrict__ vl,
              float* __restrict__ y) {
    extern __shared__ char smA[];
    const u32 sbase = smem_u32(smA);
    float* biasS = (float*)(smA + ABIAS2);

    const int tid = threadIdx.x;
    const int warp = tid >> 5, lane = tid & 31;
    const int fr = lane >> 2, fc = lane & 3;
    const int qt = blockIdx.x;          // 0..31 (64-row q tiles)
    const int bh = blockIdx.y;          // 0..63
    const int b = bh >> 4, h = bh & 15;

    const float C = 0.12751743f;        // (1/sqrt(128)) * log2(e)

    // plane byte pointers for this head
    const size_t pbase = (size_t)bh * 2048 * 256;
    const char* pkh = (const char*)kh + pbase;
    const char* pkl = (const char*)kl + pbase;
    const char* pvh = (const char*)vh + pbase;
    const char* pvl = (const char*)vl + pbase;

    // bias table for whole sequence (one-time)
    {
        const int* mg = mask + b * TT;
        for (int t = tid; t < TT; t += 128)
            biasS[t] = mg[t] ? 0.f : -1e30f;
    }

    // ---- Q fragments (hi/lo) from global ----
    u32 Qh[8][4], Ql[8][4];
    {
        const float* Qg = qkv + (size_t)(b * TT + qt * 64 + warp * 16) * (3 * DD)
                        + h * HDIM;
#pragma unroll
        for (int kf = 0; kf < 8; kf++) {
            const float* p0 = Qg + (size_t)fr * (3 * DD) + kf * 16 + 2 * fc;
            const float* p1 = p0 + (size_t)8 * (3 * DD);
            float2 v0 = *(const float2*)p0;
            float2 v1 = *(const float2*)p1;
            float2 v2 = *(const float2*)(p0 + 8);
            float2 v3 = *(const float2*)(p1 + 8);
            pack_split2(v0.x, v0.y, Qh[kf][0], Ql[kf][0]);
            pack_split2(v1.x, v1.y, Qh[kf][1], Ql[kf][1]);
            pack_split2(v2.x, v2.y, Qh[kf][2], Ql[kf][2]);
            pack_split2(v3.x, v3.y, Qh[kf][3], Ql[kf][3]);
        }
    }

    float o[16][4];
#pragma unroll
    for (int n = 0; n < 16; n++)
#pragma unroll
        for (int j = 0; j < 4; j++) o[n][j] = 0.f;
    float m0 = -1e30f, m1 = -1e30f, l0 = 0.f, l1 = 0.f;

#define AISSUE(ktc)                                                            \
    {                                                                          \
        const u32 sb_ = sbase + ((ktc) & 1) * ASTAGE2;                         \
        const size_t go_ = (size_t)(ktc) * 8192;                               \
        _Pragma("unroll")                                                      \
        for (int i_ = 0; i_ < 16; i_++) {                                      \
            int cid_ = tid + (i_ & 3) * 128;                                   \
            int row_ = cid_ >> 4, c_ = cid_ & 15;                              \
            const char* p_ = (i_ >> 2) == 0 ? pkh                              \
                           : (i_ >> 2) == 1 ? pkl                              \
                           : (i_ >> 2) == 2 ? pvh : pvl;                       \
            u32 d_ = sb_ + (u32)(i_ >> 2) * APL2 + row_ * 256 +                \
                     (((u32)(c_ ^ (row_ & 7))) << 4);                          \
            cp16(d_, p_ + go_ + row_ * 256 + c_ * 16);                         \
        }                                                                      \
        asm volatile("cp.async.commit_group;" ::: "memory");                   \
    }

    AISSUE(0);

#pragma unroll 1
    for (int kt = 0; kt < TT / 32; kt++) {
        asm volatile("cp.async.wait_group 0;" ::: "memory");
        __syncthreads();
        if (kt + 1 < TT / 32) AISSUE(kt + 1);

        const u32 sb = sbase + (kt & 1) * ASTAGE2;

        // ---- S = Q K^T (bf16x3), 32 kv cols ----
        float s[4][4];
#pragma unroll
        for (int n = 0; n < 4; n++)
#pragma unroll
            for (int j = 0; j < 4; j++) s[n][j] = 0.f;

        const int lrow8 = lane & 7;
        const int lsel = (lane >> 3) & 1;
#pragma unroll
        for (int kf = 0; kf < 8; kf++) {
#pragma unroll
            for (int n = 0; n < 4; n++) {
                int trow = n * 8 + lrow8;
                int tc = kf * 2 + lsel;
                u32 off = (u32)(trow * 256) + ((u32)(tc ^ (trow & 7)) << 4);
                u32 bhf[2], blf[2];
                ldsm_x2(bhf[0], bhf[1], sb + off);            // KH plane
                ldsm_x2(blf[0], blf[1], sb + APL2 + off);     // KL plane
                mma16816(s[n], Qh[kf], bhf);
                mma16816(s[n], Ql[kf], bhf);
                mma16816(s[n], Qh[kf], blf);
            }
        }

        // ---- online softmax (log2 domain) ----
        const float* brow = biasS + kt * 32;
        float mx0 = -1e30f, mx1 = -1e30f;
#pragma unroll
        for (int n = 0; n < 4; n++) {
            float2 bb = *(const float2*)&brow[n * 8 + 2 * fc];
            s[n][0] = fmaf(s[n][0], C, bb.x);
            s[n][1] = fmaf(s[n][1], C, bb.y);
            s[n][2] = fmaf(s[n][2], C, bb.x);
            s[n][3] = fmaf(s[n][3], C, bb.y);
            mx0 = fmaxf(mx0, fmaxf(s[n][0], s[n][1]));
            mx1 = fmaxf(mx1, fmaxf(s[n][2], s[n][3]));
        }
        mx0 = fmaxf(mx0, __shfl_xor_sync(0xffffffffu, mx0, 1));
        mx0 = fmaxf(mx0, __shfl_xor_sync(0xffffffffu, mx0, 2));
        mx1 = fmaxf(mx1, __shfl_xor_sync(0xffffffffu, mx1, 1));
        mx1 = fmaxf(mx1, __shfl_xor_sync(0xffffffffu, mx1, 2));

        float m0n = fmaxf(m0, mx0), m1n = fmaxf(m1, mx1);
        float f0 = exp2_fast(m0 - m0n), f1 = exp2_fast(m1 - m1n);
        m0 = m0n; m1 = m1n;

        float sum0 = 0.f, sum1 = 0.f;
#pragma unroll
        for (int n = 0; n < 4; n++) {
            s[n][0] = exp2_fast(s[n][0] - m0n);
            s[n][1] = exp2_fast(s[n][1] - m0n);
            s[n][2] = exp2_fast(s[n][2] - m1n);
            s[n][3] = exp2_fast(s[n][3] - m1n);
            sum0 += s[n][0] + s[n][1];
            sum1 += s[n][2] + s[n][3];
        }
        sum0 += __shfl_xor_sync(0xffffffffu, sum0, 1);
        sum0 += __shfl_xor_sync(0xffffffffu, sum0, 2);
        sum1 += __shfl_xor_sync(0xffffffffu, sum1, 1);
        sum1 += __shfl_xor_sync(0xffffffffu, sum1, 2);
        l0 = l0 * f0 + sum0;
        l1 = l1 * f1 + sum1;

#pragma unroll
        for (int n = 0; n < 16; n++) {
            o[n][0] *= f0; o[n][1] *= f0;
            o[n][2] *= f1; o[n][3] *= f1;
        }

        u32 pah[2][4], pal[2][4];
#pragma unroll
        for (int kf = 0; kf < 2; kf++) {
            pack_split2(s[2 * kf][0], s[2 * kf][1], pah[kf][0], pal[kf][0]);
            pack_split2(s[2 * kf][2], s[2 * kf][3], pah[kf][1], pal[kf][1]);
            pack_split2(s[2 * kf + 1][0], s[2 * kf + 1][1], pah[kf][2], pal[kf][2]);
            pack_split2(s[2 * kf + 1][2], s[2 * kf + 1][3], pah[kf][3], pal[kf][3]);
        }

        // ---- O += P V (bf16x3), 32 kv rows ----
        const int lrow16 = lane & 15;
#pragma unroll
        for (int n = 0; n < 16; n++) {
#pragma unroll
            for (int kf = 0; kf < 2; kf++) {
                int trow = kf * 16 + lrow16;
                u32 off = (u32)(trow * 256) + ((u32)(n ^ (trow & 7)) << 4);
                u32 bvh[2], bvl[2];
                ldsm_x2_t(bvh[0], bvh[1], sb + 2 * APL2 + off);   // VH
                ldsm_x2_t(bvl[0], bvl[1], sb + 3 * APL2 + off);   // VL
                mma16816(o[n], pah[kf], bvh);
                mma16816(o[n], pah[kf], bvl);
                mma16816(o[n], pal[kf], bvh);
            }
        }
    }
#undef AISSUE

    // ---- normalize and store (tf32-rounded) ----
    float inv0 = 1.f / l0, inv1 = 1.f / l1;
    {
        size_t r0 = (size_t)(b * TT + qt * 64 + warp * 16 + fr) * DD + h * HDIM;
        size_t r1 = r0 + (size_t)8 * DD;
#pragma unroll
        for (int n = 0; n < 16; n++) {
            int cc = n * 8 + 2 * fc;
            *(float2*)(y + r0 + cc) = make_float2(
                __uint_as_float(f2tf32(o[n][0] * inv0)),
                __uint_as_float(f2tf32(o[n][1] * inv0)));
            *(float2*)(y + r1 + cc) = make_float2(
                __uint_as_float(f2tf32(o[n][2] * inv1)),
                __uint_as_float(f2tf32(o[n][3] * inv1)));
        }
    }
}

// ---------------------------------------------------------------------------
// Launch
// ---------------------------------------------------------------------------
extern "C" void kernel_launch(void* const* d_in, const int* in_sizes, int n_in,
                              void* d_out, int out_size) {
    const float* x     = (const float*)d_in[0];
    const int*   mask  = (const int*)d_in[1];
    const float* w_qkv = (const float*)d_in[2];
    const float* w_o   = (const float*)d_in[3];
    float* out = (float*)d_out;

    float *qkv, *yb, *xr, *wq, *wo;
    u32 *kh, *kl, *vh, *vl;
    cudaGetSymbolAddress((void**)&qkv, g_qkv);
    cudaGetSymbolAddress((void**)&yb, g_y);
    cudaGetSymbolAddress((void**)&xr, g_xr);
    cudaGetSymbolAddress((void**)&wq, g_wq);
    cudaGetSymbolAddress((void**)&wo, g_wo);
    cudaGetSymbolAddress((void**)&kh, g_kh);
    cudaGetSymbolAddress((void**)&kl, g_kl);
    cudaGetSymbolAddress((void**)&vh, g_vh);
    cudaGetSymbolAddress((void**)&vl, g_vl);
    cudaFuncSetAttribute(gemm_nt_tf32p, cudaFuncAttributeMaxDynamicSharedMemorySize,
                         GEMM_SMEM3);
    cudaFuncSetAttribute(attn_mma, cudaFuncAttributeMaxDynamicSharedMemorySize,
                         ATTN4_SMEM);

    // Pre-round GEMM inputs to tf32
    {
        int n4x = (BB * TT * DD) / 4;
        int n4q = (3 * DD * DD) / 4;
        int n4o = (DD * DD) / 4;
        round_tf32<<<(n4x + 255) / 256, 256>>>(x, xr, n4x);
        round_tf32<<<(n4q + 255) / 256, 256>>>(w_qkv, wq, n4q);
        round_tf32<<<(n4o + 255) / 256, 256>>>(w_o, wo, n4o);
    }

    // QKV = X @ Wqkv^T
    gemm_nt_tf32p<<<dim3(3 * DD / 128, BB * TT / 128), 256, GEMM_SMEM3>>>(
        xr, wq, qkv, BB * TT, 3 * DD, DD);

    // Split K/V into bf16 hi/lo planes
    split_kv<<<(64 * 2048 * 16) / 256, 256>>>(qkv, kh, kl, vh, vl);

    // Attention -> y (tf32-rounded)
    attn_mma<<<dim3(TT / 64, BB * HH), 128, ATTN4_SMEM>>>(
        qkv, mask, kh, kl, vh, vl, yb);

    // out = Y @ Wo^T
    gemm_nt_tf32p<<<dim3(DD / 128, BB * TT / 128), 256, GEMM_SMEM3>>>(
        yb, wo, out, BB * TT, DD, DD);
}

// round 13
// speedup vs baseline: 1.0263x; 1.0263x over previous
#include <cuda_runtime.h>
#include <cuda_bf16.h>
#include <cstdint>
#include <math.h>

using u32 = unsigned int;

// Problem constants
#define BB 4
#define TT 2048
#define DD 2048
#define HH 16
#define HDIM 128

// Scratch (allocation-free rule: __device__ globals)
__device__ float g_qkv[(size_t)BB * TT * 3 * DD];   // (B*T, 3D) (K/V sections unused)
__device__ float g_y[(size_t)BB * TT * DD];         // (B*T, D)
__device__ float g_xr[(size_t)BB * TT * DD];        // tf32-rounded x
__device__ float g_wq[(size_t)3 * DD * DD];         // tf32-rounded w_qkv
__device__ float g_wo[(size_t)DD * DD];             // tf32-rounded w_o
// bf16 K/V planes: [(b*16+h)][t][128] bf16 (row = 256B), as u32
__device__ u32 g_kh[(size_t)64 * 2048 * 64];
__device__ u32 g_kl[(size_t)64 * 2048 * 64];
__device__ u32 g_vh[(size_t)64 * 2048 * 64];
__device__ u32 g_vl[(size_t)64 * 2048 * 64];

__device__ __forceinline__ u32 smem_u32(const void* p) {
    u32 a;
    asm("{ .reg .u64 t; cvta.to.shared.u64 t, %1; cvt.u32.u64 %0, t; }"
        : "=r"(a) : "l"(p));
    return a;
}

__device__ __forceinline__ u32 f2tf32(float f) {
    u32 u;
    asm("cvt.rna.tf32.f32 %0, %1;" : "=r"(u) : "f"(f));
    return u;
}

__device__ __forceinline__ u32 packbf(float lo, float hi) {
    u32 r;
    asm("cvt.rn.bf16x2.f32 %0, %1, %2;" : "=r"(r) : "f"(hi), "f"(lo));
    return r;
}

__device__ __forceinline__ void bsplit(float v, float& hi, float& lo) {
    __nv_bfloat16 h = __float2bfloat16_rn(v);
    hi = __bfloat162float(h);
    lo = v - hi;
}

__device__ __forceinline__ void pack_split2(float a, float b, u32& hp, u32& lp) {
    float ha, la, hb, lb;
    bsplit(a, ha, la);
    bsplit(b, hb, lb);
    hp = packbf(ha, hb);
    lp = packbf(la, lb);
}

// ---------------------------------------------------------------------------
// Pre-round pass: dst[i] = tf32_rna(src[i])
// ---------------------------------------------------------------------------
__global__ void round_tf32(const float* __restrict__ src, float* __restrict__ dst,
                           int n4) {
    int i = blockIdx.x * blockDim.x + threadIdx.x;
    if (i < n4) {
        float4 v = ((const float4*)src)[i];
        ((float4*)dst)[i] = make_float4(
            __uint_as_float(f2tf32(v.x)), __uint_as_float(f2tf32(v.y)),
            __uint_as_float(f2tf32(v.z)), __uint_as_float(f2tf32(v.w)));
    }
}

// ---------------------------------------------------------------------------
// TF32 GEMM v4: as R10 (known-pass) + fused K/V bf16-split epilogue.
// qkv_mode: K section (cols 2048..4095) -> kh/kl planes, V -> vh/vl planes.
// ---------------------------------------------------------------------------
#define GST 36
#define A_BYTES (128 * GST * 4)
#define STAGE_B (2 * A_BYTES)
#define GEMM_SMEM3 (3 * STAGE_B)
#define RCHUNK (32 * GST * 4)

__device__ __forceinline__ void mma_tf32(float* d, const u32* a, const u32* b) {
    asm volatile(
        "mma.sync.aligned.m16n8k8.row.col.f32.tf32.tf32.f32 "
        "{%0,%1,%2,%3}, {%4,%5,%6,%7}, {%8,%9}, {%0,%1,%2,%3};"
        : "+f"(d[0]), "+f"(d[1]), "+f"(d[2]), "+f"(d[3])
        : "r"(a[0]), "r"(a[1]), "r"(a[2]), "r"(a[3]), "r"(b[0]), "r"(b[1]));
}

__device__ __forceinline__ void ldmx4(u32* r, u32 addr) {
    asm volatile("ldmatrix.sync.aligned.m8n8.x4.shared.b16 {%0,%1,%2,%3}, [%4];"
                 : "=r"(r[0]), "=r"(r[1]), "=r"(r[2]), "=r"(r[3]) : "r"(addr));
}

__device__ __forceinline__ void cp16(u32 dst, const void* src) {
    asm volatile("cp.async.cg.shared.global [%0], [%1], 16;"
                 :: "r"(dst), "l"(src) : "memory");
}

__global__ __launch_bounds__(256, 2)
void gemm_nt_tf32p(const float* __restrict__ A, const float* __restrict__ B,
                   float* __restrict__ C, int M, int N, int K,
                   u32* __restrict__ kh, u32* __restrict__ kl,
                   u32* __restrict__ vh, u32* __restrict__ vl, int qkv_mode) {
    extern __shared__ char sm3[];
    const u32 sbase = smem_u32(sm3);
    const int tid = threadIdx.x;
    const int warp = tid >> 5, lane = tid & 31;
    const int wm = warp >> 1, wn = warp & 1;
    const int fr = lane >> 2, fc = lane & 3;
    const int row0 = blockIdx.y * 128, col0 = blockIdx.x * 128;

    const int lrow = tid >> 3, lcc = tid & 7;
    const u32 so0 = (u32)(lrow * GST + lcc * 4) * 4;
    const float* ga0 = A + (size_t)(row0 + lrow) * K + lcc * 4;
    const float* gb0 = B + (size_t)(col0 + lrow) * K + lcc * 4;
    const size_t rstep = (size_t)32 * K;

    const int gl = lane >> 3, lr8 = lane & 7;
    const u32 afrag = (u32)((wm * 32 + (gl & 1) * 8 + lr8) * GST + (gl >> 1) * 4) * 4;
    const u32 bfrag = A_BYTES +
        (u32)((wn * 64 + (gl >> 1) * 8 + lr8) * GST + (gl & 1) * 4) * 4;

    float acc[2][8][4];
#pragma unroll
    for (int mf = 0; mf < 2; mf++)
#pragma unroll
        for (int g = 0; g < 8; g++)
#pragma unroll
            for (int i = 0; i < 4; i++) acc[mf][g][i] = 0.f;

    const int nslabs = K / 32;

#define ISSUE(slab)                                                          \
    {                                                                        \
        const int st_ = (slab) % 3;                                          \
        const int k0_ = (slab) * 32;                                         \
        const u32 sb_ = sbase + st_ * STAGE_B;                               \
        _Pragma("unroll")                                                    \
        for (int s_ = 0; s_ < 4; s_++) {                                     \
            cp16(sb_ + so0 + RCHUNK * s_, ga0 + rstep * s_ + k0_);           \
            cp16(sb_ + A_BYTES + so0 + RCHUNK * s_, gb0 + rstep * s_ + k0_); \
        }                                                                    \
        asm volatile("cp.async.commit_group;" ::: "memory");                 \
    }

    ISSUE(0);
    ISSUE(1);

#pragma unroll 1
    for (int c = 0; c < nslabs; c++) {
        if (c + 1 < nslabs)
            asm volatile("cp.async.wait_group 1;" ::: "memory");
        else
            asm volatile("cp.async.wait_group 0;" ::: "memory");
        __syncthreads();
        if (c + 2 < nslabs) ISSUE(c + 2);

        const u32 sb = sbase + (c % 3) * STAGE_B;
#pragma unroll
        for (int ks = 0; ks < 32; ks += 8) {
            u32 a[2][4], b[8][2];
            ldmx4(a[0], sb + afrag + ks * 4);
            ldmx4(a[1], sb + afrag + 16 * GST * 4 + ks * 4);
#pragma unroll
            for (int j = 0; j < 4; j++) {
                u32 r[4];
                ldmx4(r, sb + bfrag + j * 16 * GST * 4 + ks * 4);
                b[2 * j][0] = r[0]; b[2 * j][1] = r[1];
                b[2 * j + 1][0] = r[2]; b[2 * j + 1][1] = r[3];
            }
#pragma unroll
            for (int mf = 0; mf < 2; mf++)
#pragma unroll
                for (int g = 0; g < 8; g++)
                    mma_tf32(acc[mf][g], a[mf], b[g]);
        }
    }

    // Epilogue
    if (qkv_mode && col0 >= 2048) {
        // K or V section: split to bf16 hi/lo planes (same math as split_kv)
        const int sec = col0 >> 11;                 // 1=K, 2=V
        u32* __restrict__ ph = (sec == 1) ? kh : vh;
        u32* __restrict__ pl = (sec == 1) ? kl : vl;
        const int h = (col0 >> 7) & 15;
#pragma unroll
        for (int mf = 0; mf < 2; mf++) {
#pragma unroll
            for (int g = 0; g < 8; g++) {
                int rr = row0 + wm * 32 + mf * 16 + fr;
                int cc = col0 + wn * 64 + g * 8 + 2 * fc;
                int cu = (cc & 127) >> 1;
                {
                    int bb = rr >> 11, tok = rr & 2047;
                    size_t base = ((size_t)(bb * 16 + h) * 2048 + tok) * 64 + cu;
                    u32 hp, lp;
                    pack_split2(acc[mf][g][0], acc[mf][g][1], hp, lp);
                    ph[base] = hp; pl[base] = lp;
                }
                {
                    int rr2 = rr + 8;
                    int bb = rr2 >> 11, tok = rr2 & 2047;
                    size_t base = ((size_t)(bb * 16 + h) * 2048 + tok) * 64 + cu;
                    u32 hp, lp;
                    pack_split2(acc[mf][g][2], acc[mf][g][3], hp, lp);
                    ph[base] = hp; pl[base] = lp;
                }
            }
        }
    } else {
#pragma unroll
        for (int mf = 0; mf < 2; mf++) {
#pragma unroll
            for (int g = 0; g < 8; g++) {
                int rr = row0 + wm * 32 + mf * 16 + fr;
                int cc = col0 + wn * 64 + g * 8 + 2 * fc;
                *(float2*)(C + (size_t)rr * N + cc) =
                    make_float2(acc[mf][g][0], acc[mf][g][1]);
                *(float2*)(C + (size_t)(rr + 8) * N + cc) =
                    make_float2(acc[mf][g][2], acc[mf][g][3]);
            }
        }
    }
#undef ISSUE
}

// ===========================================================================
// Flash attention v6 = R11 structure (256 thr, 128 q-rows, kv chunk 64,
// 2-stage cp.async) + register double-buffered B-fragments (ldsm prefetch).
// ===========================================================================
#define APL 16384                      // bytes per plane per stage
#define ASTAGE (4 * APL)               // 65536
#define ABIAS_OFF (2 * ASTAGE)
#define ATTN3_SMEM (2 * ASTAGE + 2048 * 4)

__device__ __forceinline__ void mma16816(float* c, const u32* a, const u32* b) {
    asm volatile(
        "mma.sync.aligned.m16n8k16.row.col.f32.bf16.bf16.f32 "
        "{%0,%1,%2,%3}, {%4,%5,%6,%7}, {%8,%9}, {%0,%1,%2,%3};"
        : "+f"(c[0]), "+f"(c[1]), "+f"(c[2]), "+f"(c[3])
        : "r"(a[0]), "r"(a[1]), "r"(a[2]), "r"(a[3]), "r"(b[0]), "r"(b[1]));
}

__device__ __forceinline__ void ldsm_x2(u32& r0, u32& r1, u32 addr) {
    asm volatile("ldmatrix.sync.aligned.m8n8.x2.shared.b16 {%0,%1}, [%2];"
                 : "=r"(r0), "=r"(r1) : "r"(addr));
}

__device__ __forceinline__ void ldsm_x2_t(u32& r0, u32& r1, u32 addr) {
    asm volatile("ldmatrix.sync.aligned.m8n8.x2.trans.shared.b16 {%0,%1}, [%2];"
                 : "=r"(r0), "=r"(r1) : "r"(addr));
}

__device__ __forceinline__ float exp2_fast(float t) {
    t = fmaxf(t, -126.f);
    float k = rintf(t);
    float f = t - k;
    float u = f * 0.69314718056f;
    float p = 0.0013888889f;
    p = fmaf(p, u, 0.008333334f);
    p = fmaf(p, u, 0.041666668f);
    p = fmaf(p, u, 0.16666667f);
    p = fmaf(p, u, 0.5f);
    p = fmaf(p, u, 1.0f);
    p = fmaf(p, u, 1.0f);
    return __int_as_float(((int)k + 127) << 23) * p;
}

__global__ __launch_bounds__(256)
void attn_mma(const float* __restrict__ qkv, const int* __restrict__ mask,
              const u32* __restrict__ kh, const u32* __restrict__ kl,
              const u32* __restrict__ vh, const u32* __restrict__ vl,
              float* __restrict__ y) {
    extern __shared__ char smA[];
    const u32 sbase = smem_u32(smA);
    float* biasS = (float*)(smA + ABIAS_OFF);

    const int tid = threadIdx.x;
    const int warp = tid >> 5, lane = tid & 31;
    const int fr = lane >> 2, fc = lane & 3;
    const int qt = blockIdx.x;          // 0..15 (128-row q tiles)
    const int bh = blockIdx.y;          // 0..63
    const int b = bh >> 4, h = bh & 15;

    const float C = 0.12751743f;        // (1/sqrt(128)) * log2(e)

    const size_t pbase = (size_t)bh * 2048 * 256;
    const char* pkh = (const char*)kh + pbase;
    const char* pkl = (const char*)kl + pbase;
    const char* pvh = (const char*)vh + pbase;
    const char* pvl = (const char*)vl + pbase;

    {
        const int* mg = mask + b * TT;
        for (int t = tid; t < TT; t += 256)
            biasS[t] = mg[t] ? 0.f : -1e30f;
    }

    // ---- Q fragments (hi/lo) from global ----
    u32 Qh[8][4], Ql[8][4];
    {
        const float* Qg = qkv + (size_t)(b * TT + qt * 128 + warp * 16) * (3 * DD)
                        + h * HDIM;
#pragma unroll
        for (int kf = 0; kf < 8; kf++) {
            const float* p0 = Qg + (size_t)fr * (3 * DD) + kf * 16 + 2 * fc;
            const float* p1 = p0 + (size_t)8 * (3 * DD);
            float2 v0 = *(const float2*)p0;
            float2 v1 = *(const float2*)p1;
            float2 v2 = *(const float2*)(p0 + 8);
            float2 v3 = *(const float2*)(p1 + 8);
            pack_split2(v0.x, v0.y, Qh[kf][0], Ql[kf][0]);
            pack_split2(v1.x, v1.y, Qh[kf][1], Ql[kf][1]);
            pack_split2(v2.x, v2.y, Qh[kf][2], Ql[kf][2]);
            pack_split2(v3.x, v3.y, Qh[kf][3], Ql[kf][3]);
        }
    }

    float o[16][4];
#pragma unroll
    for (int n = 0; n < 16; n++)
#pragma unroll
        for (int j = 0; j < 4; j++) o[n][j] = 0.f;
    float m0 = -1e30f, m1 = -1e30f, l0 = 0.f, l1 = 0.f;

#define AISSUE(ktc)                                                            \
    {                                                                          \
        const u32 sb_ = sbase + ((ktc) & 1) * ASTAGE;                          \
        const size_t go_ = (size_t)(ktc) * 16384;                              \
        _Pragma("unroll")                                                      \
        for (int i_ = 0; i_ < 16; i_++) {                                      \
            int cid_ = tid + (i_ & 3) * 256;                                   \
            int row_ = cid_ >> 4, c_ = cid_ & 15;                              \
            const char* p_ = (i_ >> 2) == 0 ? pkh                              \
                           : (i_ >> 2) == 1 ? pkl                              \
                           : (i_ >> 2) == 2 ? pvh : pvl;                       \
            u32 d_ = sb_ + (u32)(i_ >> 2) * APL + row_ * 256 +                 \
                     (((u32)(c_ ^ (row_ & 7))) << 4);                          \
            cp16(d_, p_ + go_ + row_ * 256 + c_ * 16);                         \
        }                                                                      \
        asm volatile("cp.async.commit_group;" ::: "memory");                   \
    }

    AISSUE(0);

    const int lrow8 = lane & 7;
    const int lsel = (lane >> 3) & 1;
    const int lrow16 = lane & 15;

// K fragment smem offset for (kf, n); trow&7 == lrow8
#define KOFF(kf_, n_) \
    ((u32)(((n_) * 8 + lrow8) * 256) + ((u32)(((kf_) * 2 + lsel) ^ lrow8) << 4))
// V fragment smem offset for (n, kf); trow&7 == lrow16&7
#define VOFF(n_, kf_) \
    ((u32)(((kf_) * 16 + lrow16) * 256) + ((u32)((n_) ^ (lrow16 & 7)) << 4))

#pragma unroll 1
    for (int kt = 0; kt < TT / 64; kt++) {
        asm volatile("cp.async.wait_group 0;" ::: "memory");
        __syncthreads();
        if (kt + 1 < TT / 64) AISSUE(kt + 1);

        const u32 sb = sbase + (kt & 1) * ASTAGE;

        // ---- S = Q K^T (bf16x3), B-fragments double-buffered ----
        float s[8][4];
#pragma unroll
        for (int n = 0; n < 8; n++)
#pragma unroll
            for (int j = 0; j < 4; j++) s[n][j] = 0.f;

        {
            u32 bhf[2][2], blf[2][2];
            u32 off0 = KOFF(0, 0);
            ldsm_x2(bhf[0][0], bhf[0][1], sb + off0);
            ldsm_x2(blf[0][0], blf[0][1], sb + APL + off0);
#pragma unroll
            for (int idx = 0; idx < 64; idx++) {
                const int kf = idx >> 3, n = idx & 7;
                const int cur = idx & 1, nxt = cur ^ 1;
                if (idx < 63) {
                    const int i2 = idx + 1;
                    u32 off = KOFF(i2 >> 3, i2 & 7);
                    ldsm_x2(bhf[nxt][0], bhf[nxt][1], sb + off);
                    ldsm_x2(blf[nxt][0], blf[nxt][1], sb + APL + off);
                }
                mma16816(s[n], Qh[kf], bhf[cur]);
                mma16816(s[n], Ql[kf], bhf[cur]);
                mma16816(s[n], Qh[kf], blf[cur]);
            }
        }

        // ---- online softmax (log2 domain) ----
        const float* brow = biasS + kt * 64;
        float mx0 = -1e30f, mx1 = -1e30f;
#pragma unroll
        for (int n = 0; n < 8; n++) {
            float2 bb = *(const float2*)&brow[n * 8 + 2 * fc];
            s[n][0] = fmaf(s[n][0], C, bb.x);
            s[n][1] = fmaf(s[n][1], C, bb.y);
            s[n][2] = fmaf(s[n][2], C, bb.x);
            s[n][3] = fmaf(s[n][3], C, bb.y);
            mx0 = fmaxf(mx0, fmaxf(s[n][0], s[n][1]));
            mx1 = fmaxf(mx1, fmaxf(s[n][2], s[n][3]));
        }
        mx0 = fmaxf(mx0, __shfl_xor_sync(0xffffffffu, mx0, 1));
        mx0 = fmaxf(mx0, __shfl_xor_sync(0xffffffffu, mx0, 2));
        mx1 = fmaxf(mx1, __shfl_xor_sync(0xffffffffu, mx1, 1));
        mx1 = fmaxf(mx1, __shfl_xor_sync(0xffffffffu, mx1, 2));

        float m0n = fmaxf(m0, mx0), m1n = fmaxf(m1, mx1);
        float f0 = exp2_fast(m0 - m0n), f1 = exp2_fast(m1 - m1n);
        m0 = m0n; m1 = m1n;

        float sum0 = 0.f, sum1 = 0.f;
#pragma unroll
        for (int n = 0; n < 8; n++) {
            s[n][0] = exp2_fast(s[n][0] - m0n);
            s[n][1] = exp2_fast(s[n][1] - m0n);
            s[n][2] = exp2_fast(s[n][2] - m1n);
            s[n][3] = exp2_fast(s[n][3] - m1n);
            sum0 += s[n][0] + s[n][1];
            sum1 += s[n][2] + s[n][3];
        }
        sum0 += __shfl_xor_sync(0xffffffffu, sum0, 1);
        sum0 += __shfl_xor_sync(0xffffffffu, sum0, 2);
        sum1 += __shfl_xor_sync(0xffffffffu, sum1, 1);
        sum1 += __shfl_xor_sync(0xffffffffu, sum1, 2);
        l0 = l0 * f0 + sum0;
        l1 = l1 * f1 + sum1;

#pragma unroll
        for (int n = 0; n < 16; n++) {
            o[n][0] *= f0; o[n][1] *= f0;
            o[n][2] *= f1; o[n][3] *= f1;
        }

        u32 pah[4][4], pal[4][4];
#pragma unroll
        for (int kf = 0; kf < 4; kf++) {
            pack_split2(s[2 * kf][0], s[2 * kf][1], pah[kf][0], pal[kf][0]);
            pack_split2(s[2 * kf][2], s[2 * kf][3], pah[kf][1], pal[kf][1]);
            pack_split2(s[2 * kf + 1][0], s[2 * kf + 1][1], pah[kf][2], pal[kf][2]);
            pack_split2(s[2 * kf + 1][2], s[2 * kf + 1][3], pah[kf][3], pal[kf][3]);
        }

        // ---- O += P V (bf16x3), B-fragments double-buffered ----
        {
            u32 bvh[2][2], bvl[2][2];
            u32 off0 = VOFF(0, 0);
            ldsm_x2_t(bvh[0][0], bvh[0][1], sb + 2 * APL + off0);
            ldsm_x2_t(bvl[0][0], bvl[0][1], sb + 3 * APL + off0);
#pragma unroll
            for (int idx = 0; idx < 64; idx++) {
                const int n = idx >> 2, kf = idx & 3;
                const int cur = idx & 1, nxt = cur ^ 1;
                if (idx < 63) {
                    const int i2 = idx + 1;
                    u32 off = VOFF(i2 >> 2, i2 & 3);
                    ldsm_x2_t(bvh[nxt][0], bvh[nxt][1], sb + 2 * APL + off);
                    ldsm_x2_t(bvl[nxt][0], bvl[nxt][1], sb + 3 * APL + off);
                }
                mma16816(o[n], pah[kf], bvh[cur]);
                mma16816(o[n], pah[kf], bvl[cur]);
                mma16816(o[n], pal[kf], bvh[cur]);
            }
        }
    }
#undef AISSUE
#undef KOFF
#undef VOFF

    // ---- normalize and store (tf32-rounded) ----
    float inv0 = 1.f / l0, inv1 = 1.f / l1;
    {
        size_t r0 = (size_t)(b * TT + qt * 128 + warp * 16 + fr) * DD + h * HDIM;
        size_t r1 = r0 + (size_t)8 * DD;
#pragma unroll
        for (int n = 0; n < 16; n++) {
            int cc = n * 8 + 2 * fc;
            *(float2*)(y + r0 + cc) = make_float2(
                __uint_as_float(f2tf32(o[n][0] * inv0)),
                __uint_as_float(f2tf32(o[n][1] * inv0)));
            *(float2*)(y + r1 + cc) = make_float2(
                __uint_as_float(f2tf32(o[n][2] * inv1)),
                __uint_as_float(f2tf32(o[n][3] * inv1)));
        }
    }
}

// ---------------------------------------------------------------------------
// Launch
// ---------------------------------------------------------------------------
extern "C" void kernel_launch(void* const* d_in, const int* in_sizes, int n_in,
                              void* d_out, int out_size) {
    const float* x     = (const float*)d_in[0];
    const int*   mask  = (const int*)d_in[1];
    const float* w_qkv = (const float*)d_in[2];
    const float* w_o   = (const float*)d_in[3];
    float* out = (float*)d_out;

    float *qkv, *yb, *xr, *wq, *wo;
    u32 *kh, *kl, *vh, *vl;
    cudaGetSymbolAddress((void**)&qkv, g_qkv);
    cudaGetSymbolAddress((void**)&yb, g_y);
    cudaGetSymbolAddress((void**)&xr, g_xr);
    cudaGetSymbolAddress((void**)&wq, g_wq);
    cudaGetSymbolAddress((void**)&wo, g_wo);
    cudaGetSymbolAddress((void**)&kh, g_kh);
    cudaGetSymbolAddress((void**)&kl, g_kl);
    cudaGetSymbolAddress((void**)&vh, g_vh);
    cudaGetSymbolAddress((void**)&vl, g_vl);
    cudaFuncSetAttribute(gemm_nt_tf32p, cudaFuncAttributeMaxDynamicSharedMemorySize,
                         GEMM_SMEM3);
    cudaFuncSetAttribute(attn_mma, cudaFuncAttributeMaxDynamicSharedMemorySize,
                         ATTN3_SMEM);

    // Pre-round GEMM inputs to tf32
    {
        int n4x = (BB * TT * DD) / 4;
        int n4q = (3 * DD * DD) / 4;
        int n4o = (DD * DD) / 4;
        round_tf32<<<(n4x + 255) / 256, 256>>>(x, xr, n4x);
        round_tf32<<<(n4q + 255) / 256, 256>>>(w_qkv, wq, n4q);
        round_tf32<<<(n4o + 255) / 256, 256>>>(w_o, wo, n4o);
    }

    // QKV = X @ Wqkv^T, K/V sections split to bf16 planes in-epilogue
    gemm_nt_tf32p<<<dim3(3 * DD / 128, BB * TT / 128), 256, GEMM_SMEM3>>>(
        xr, wq, qkv, BB * TT, 3 * DD, DD, kh, kl, vh, vl, 1);

    // Attention -> y (tf32-rounded)
    attn_mma<<<dim3(TT / 128, BB * HH), 256, ATTN3_SMEM>>>(
        qkv, mask, kh, kl, vh, vl, yb);

    // out = Y @ Wo^T
    gemm_nt_tf32p<<<dim3(DD / 128, BB * TT / 128), 256, GEMM_SMEM3>>>(
        yb, wo, out, BB * TT, DD, DD, nullptr, nullptr, nullptr, nullptr, 0);
}

// round 14
// speedup vs baseline: 1.1511x; 1.1216x over previous
#include <cuda_runtime.h>
#include <cuda_fp16.h>
#include <cstdint>
#include <math.h>

using u32 = unsigned int;

// Problem constants
#define BB 4
#define TT 2048
#define DD 2048
#define HH 16
#define HDIM 128

// Scratch (allocation-free rule: __device__ globals)
__device__ float g_qkv[(size_t)BB * TT * 3 * DD];   // (B*T, 3D) (K/V sections unused)
__device__ float g_y[(size_t)BB * TT * DD];         // (B*T, D)
__device__ float g_xr[(size_t)BB * TT * DD];        // tf32-rounded x
__device__ float g_wq[(size_t)3 * DD * DD];         // tf32-rounded w_qkv
__device__ float g_wo[(size_t)DD * DD];             // tf32-rounded w_o
// fp16 K/V planes: [(b*16+h)][t][128] half (row = 256B), as u32
__device__ u32 g_kh[(size_t)64 * 2048 * 64];
__device__ u32 g_kl[(size_t)64 * 2048 * 64];
__device__ u32 g_vh[(size_t)64 * 2048 * 64];

__device__ __forceinline__ u32 smem_u32(const void* p) {
    u32 a;
    asm("{ .reg .u64 t; cvta.to.shared.u64 t, %1; cvt.u32.u64 %0, t; }"
        : "=r"(a) : "l"(p));
    return a;
}

__device__ __forceinline__ u32 f2tf32(float f) {
    u32 u;
    asm("cvt.rna.tf32.f32 %0, %1;" : "=r"(u) : "f"(f));
    return u;
}

// pack two fp32 into f16x2 (lo in low half, hi in high half)
__device__ __forceinline__ u32 packf16(float lo, float hi) {
    u32 r;
    asm("cvt.rn.f16x2.f32 %0, %1, %2;" : "=r"(r) : "f"(hi), "f"(lo));
    return r;
}

__device__ __forceinline__ void hsplit(float v, float& hi, float& lo) {
    __half h = __float2half_rn(v);
    hi = __half2float(h);
    lo = v - hi;
}

// two fp32 -> hi-pair f16x2 and lo-pair f16x2
__device__ __forceinline__ void pack_hsplit2(float a, float b, u32& hp, u32& lp) {
    float ha, la, hb, lb;
    hsplit(a, ha, la);
    hsplit(b, hb, lb);
    hp = packf16(ha, hb);
    lp = packf16(la, lb);
}

// ---------------------------------------------------------------------------
// Pre-round pass: dst[i] = tf32_rna(src[i])
// ---------------------------------------------------------------------------
__global__ void round_tf32(const float* __restrict__ src, float* __restrict__ dst,
                           int n4) {
    int i = blockIdx.x * blockDim.x + threadIdx.x;
    if (i < n4) {
        float4 v = ((const float4*)src)[i];
        ((float4*)dst)[i] = make_float4(
            __uint_as_float(f2tf32(v.x)), __uint_as_float(f2tf32(v.y)),
            __uint_as_float(f2tf32(v.z)), __uint_as_float(f2tf32(v.w)));
    }
}

// ---------------------------------------------------------------------------
// TF32 GEMM (R10 core, known-pass) + fused K/V fp16-split epilogue.
// K section (cols 2048..4095) -> kh/kl planes; V section -> vh plane.
// ---------------------------------------------------------------------------
#define GST 36
#define A_BYTES (128 * GST * 4)
#define STAGE_B (2 * A_BYTES)
#define GEMM_SMEM3 (3 * STAGE_B)
#define RCHUNK (32 * GST * 4)

__device__ __forceinline__ void mma_tf32(float* d, const u32* a, const u32* b) {
    asm volatile(
        "mma.sync.aligned.m16n8k8.row.col.f32.tf32.tf32.f32 "
        "{%0,%1,%2,%3}, {%4,%5,%6,%7}, {%8,%9}, {%0,%1,%2,%3};"
        : "+f"(d[0]), "+f"(d[1]), "+f"(d[2]), "+f"(d[3])
        : "r"(a[0]), "r"(a[1]), "r"(a[2]), "r"(a[3]), "r"(b[0]), "r"(b[1]));
}

__device__ __forceinline__ void ldmx4(u32* r, u32 addr) {
    asm volatile("ldmatrix.sync.aligned.m8n8.x4.shared.b16 {%0,%1,%2,%3}, [%4];"
                 : "=r"(r[0]), "=r"(r[1]), "=r"(r[2]), "=r"(r[3]) : "r"(addr));
}

__device__ __forceinline__ void cp16(u32 dst, const void* src) {
    asm volatile("cp.async.cg.shared.global [%0], [%1], 16;"
                 :: "r"(dst), "l"(src) : "memory");
}

__global__ __launch_bounds__(256, 2)
void gemm_nt_tf32p(const float* __restrict__ A, const float* __restrict__ B,
                   float* __restrict__ C, int M, int N, int K,
                   u32* __restrict__ kh, u32* __restrict__ kl,
                   u32* __restrict__ vh, int qkv_mode) {
    extern __shared__ char sm3[];
    const u32 sbase = smem_u32(sm3);
    const int tid = threadIdx.x;
    const int warp = tid >> 5, lane = tid & 31;
    const int wm = warp >> 1, wn = warp & 1;
    const int fr = lane >> 2, fc = lane & 3;
    const int row0 = blockIdx.y * 128, col0 = blockIdx.x * 128;

    const int lrow = tid >> 3, lcc = tid & 7;
    const u32 so0 = (u32)(lrow * GST + lcc * 4) * 4;
    const float* ga0 = A + (size_t)(row0 + lrow) * K + lcc * 4;
    const float* gb0 = B + (size_t)(col0 + lrow) * K + lcc * 4;
    const size_t rstep = (size_t)32 * K;

    const int gl = lane >> 3, lr8 = lane & 7;
    const u32 afrag = (u32)((wm * 32 + (gl & 1) * 8 + lr8) * GST + (gl >> 1) * 4) * 4;
    const u32 bfrag = A_BYTES +
        (u32)((wn * 64 + (gl >> 1) * 8 + lr8) * GST + (gl & 1) * 4) * 4;

    float acc[2][8][4];
#pragma unroll
    for (int mf = 0; mf < 2; mf++)
#pragma unroll
        for (int g = 0; g < 8; g++)
#pragma unroll
            for (int i = 0; i < 4; i++) acc[mf][g][i] = 0.f;

    const int nslabs = K / 32;

#define ISSUE(slab)                                                          \
    {                                                                        \
        const int st_ = (slab) % 3;                                          \
        const int k0_ = (slab) * 32;                                         \
        const u32 sb_ = sbase + st_ * STAGE_B;                               \
        _Pragma("unroll")                                                    \
        for (int s_ = 0; s_ < 4; s_++) {                                     \
            cp16(sb_ + so0 + RCHUNK * s_, ga0 + rstep * s_ + k0_);           \
            cp16(sb_ + A_BYTES + so0 + RCHUNK * s_, gb0 + rstep * s_ + k0_); \
        }                                                                    \
        asm volatile("cp.async.commit_group;" ::: "memory");                 \
    }

    ISSUE(0);
    ISSUE(1);

#pragma unroll 1
    for (int c = 0; c < nslabs; c++) {
        if (c + 1 < nslabs)
            asm volatile("cp.async.wait_group 1;" ::: "memory");
        else
            asm volatile("cp.async.wait_group 0;" ::: "memory");
        __syncthreads();
        if (c + 2 < nslabs) ISSUE(c + 2);

        const u32 sb = sbase + (c % 3) * STAGE_B;
#pragma unroll
        for (int ks = 0; ks < 32; ks += 8) {
            u32 a[2][4], b[8][2];
            ldmx4(a[0], sb + afrag + ks * 4);
            ldmx4(a[1], sb + afrag + 16 * GST * 4 + ks * 4);
#pragma unroll
            for (int j = 0; j < 4; j++) {
                u32 r[4];
                ldmx4(r, sb + bfrag + j * 16 * GST * 4 + ks * 4);
                b[2 * j][0] = r[0]; b[2 * j][1] = r[1];
                b[2 * j + 1][0] = r[2]; b[2 * j + 1][1] = r[3];
            }
#pragma unroll
            for (int mf = 0; mf < 2; mf++)
#pragma unroll
                for (int g = 0; g < 8; g++)
                    mma_tf32(acc[mf][g], a[mf], b[g]);
        }
    }

    // Epilogue
    if (qkv_mode && col0 >= 2048) {
        const int sec = col0 >> 11;                 // 1=K, 2=V
        const int h = (col0 >> 7) & 15;
#pragma unroll
        for (int mf = 0; mf < 2; mf++) {
#pragma unroll
            for (int g = 0; g < 8; g++) {
                int rr = row0 + wm * 32 + mf * 16 + fr;
                int cc = col0 + wn * 64 + g * 8 + 2 * fc;
                int cu = (cc & 127) >> 1;
#pragma unroll
                for (int half = 0; half < 2; half++) {
                    int r2 = rr + half * 8;
                    int bb = r2 >> 11, tok = r2 & 2047;
                    size_t base = ((size_t)(bb * 16 + h) * 2048 + tok) * 64 + cu;
                    float a0 = acc[mf][g][half * 2], a1 = acc[mf][g][half * 2 + 1];
                    if (sec == 1) {
                        u32 hp, lp;
                        pack_hsplit2(a0, a1, hp, lp);
                        kh[base] = hp;
                        kl[base] = lp;
                    } else {
                        vh[base] = packf16(a0, a1);
                    }
                }
            }
        }
    } else {
#pragma unroll
        for (int mf = 0; mf < 2; mf++) {
#pragma unroll
            for (int g = 0; g < 8; g++) {
                int rr = row0 + wm * 32 + mf * 16 + fr;
                int cc = col0 + wn * 64 + g * 8 + 2 * fc;
                *(float2*)(C + (size_t)rr * N + cc) =
                    make_float2(acc[mf][g][0], acc[mf][g][1]);
                *(float2*)(C + (size_t)(rr + 8) * N + cc) =
                    make_float2(acc[mf][g][2], acc[mf][g][3]);
            }
        }
    }
#undef ISSUE
}

// ===========================================================================
// Flash attention v7: fp16 arithmetic.
// QK^T: QhKh + QlKh + QhKl (fp16 two-term split, error ~eps^2).
// PV:   single P(fp16) x V(fp16) mma (error ~2.4e-4, R6-calibrated).
// 256 thr, 128 q-rows/CTA, kv chunk 64, 2-stage cp.async, 3 smem planes.
// ===========================================================================
#define APL 16384                      // bytes per plane per stage
#define ASTAGE (3 * APL)               // 49152
#define ABIAS_OFF (2 * ASTAGE)         // 98304
#define ATTN3_SMEM (2 * ASTAGE + 2048 * 4)

__device__ __forceinline__ void mma_f16(float* c, const u32* a, const u32* b) {
    asm volatile(
        "mma.sync.aligned.m16n8k16.row.col.f32.f16.f16.f32 "
        "{%0,%1,%2,%3}, {%4,%5,%6,%7}, {%8,%9}, {%0,%1,%2,%3};"
        : "+f"(c[0]), "+f"(c[1]), "+f"(c[2]), "+f"(c[3])
        : "r"(a[0]), "r"(a[1]), "r"(a[2]), "r"(a[3]), "r"(b[0]), "r"(b[1]));
}

__device__ __forceinline__ void ldsm_x2(u32& r0, u32& r1, u32 addr) {
    asm volatile("ldmatrix.sync.aligned.m8n8.x2.shared.b16 {%0,%1}, [%2];"
                 : "=r"(r0), "=r"(r1) : "r"(addr));
}

__device__ __forceinline__ void ldsm_x2_t(u32& r0, u32& r1, u32 addr) {
    asm volatile("ldmatrix.sync.aligned.m8n8.x2.trans.shared.b16 {%0,%1}, [%2];"
                 : "=r"(r0), "=r"(r1) : "r"(addr));
}

__device__ __forceinline__ float exp2_fast(float t) {
    t = fmaxf(t, -126.f);
    float k = rintf(t);
    float f = t - k;
    float u = f * 0.69314718056f;
    float p = 0.0013888889f;
    p = fmaf(p, u, 0.008333334f);
    p = fmaf(p, u, 0.041666668f);
    p = fmaf(p, u, 0.16666667f);
    p = fmaf(p, u, 0.5f);
    p = fmaf(p, u, 1.0f);
    p = fmaf(p, u, 1.0f);
    return __int_as_float(((int)k + 127) << 23) * p;
}

__global__ __launch_bounds__(256)
void attn_mma(const float* __restrict__ qkv, const int* __restrict__ mask,
              const u32* __restrict__ kh, const u32* __restrict__ kl,
              const u32* __restrict__ vh, float* __restrict__ y) {
    extern __shared__ char smA[];
    const u32 sbase = smem_u32(smA);
    float* biasS = (float*)(smA + ABIAS_OFF);

    const int tid = threadIdx.x;
    const int warp = tid >> 5, lane = tid & 31;
    const int fr = lane >> 2, fc = lane & 3;
    const int qt = blockIdx.x;          // 0..15
    const int bh = blockIdx.y;          // 0..63
    const int b = bh >> 4, h = bh & 15;

    const float C = 0.12751743f;        // (1/sqrt(128)) * log2(e)

    const size_t pbase = (size_t)bh * 2048 * 256;
    const char* pkh = (const char*)kh + pbase;
    const char* pkl = (const char*)kl + pbase;
    const char* pvh = (const char*)vh + pbase;

    {
        const int* mg = mask + b * TT;
        for (int t = tid; t < TT; t += 256)
            biasS[t] = mg[t] ? 0.f : -1e30f;
    }

    // ---- Q fragments (fp16 hi/lo) from global ----
    u32 Qh[8][4], Ql[8][4];
    {
        const float* Qg = qkv + (size_t)(b * TT + qt * 128 + warp * 16) * (3 * DD)
                        + h * HDIM;
#pragma unroll
        for (int kf = 0; kf < 8; kf++) {
            const float* p0 = Qg + (size_t)fr * (3 * DD) + kf * 16 + 2 * fc;
            const float* p1 = p0 + (size_t)8 * (3 * DD);
            float2 v0 = *(const float2*)p0;
            float2 v1 = *(const float2*)p1;
            float2 v2 = *(const float2*)(p0 + 8);
            float2 v3 = *(const float2*)(p1 + 8);
            pack_hsplit2(v0.x, v0.y, Qh[kf][0], Ql[kf][0]);
            pack_hsplit2(v1.x, v1.y, Qh[kf][1], Ql[kf][1]);
            pack_hsplit2(v2.x, v2.y, Qh[kf][2], Ql[kf][2]);
            pack_hsplit2(v3.x, v3.y, Qh[kf][3], Ql[kf][3]);
        }
    }

    float o[16][4];
#pragma unroll
    for (int n = 0; n < 16; n++)
#pragma unroll
        for (int j = 0; j < 4; j++) o[n][j] = 0.f;
    float m0 = -1e30f, m1 = -1e30f, l0 = 0.f, l1 = 0.f;

#define AISSUE(ktc)                                                            \
    {                                                                          \
        const u32 sb_ = sbase + ((ktc) & 1) * ASTAGE;                          \
        const size_t go_ = (size_t)(ktc) * 16384;                              \
        _Pragma("unroll")                                                      \
        for (int i_ = 0; i_ < 12; i_++) {                                      \
            int cid_ = tid + (i_ & 3) * 256;                                   \
            int row_ = cid_ >> 4, c_ = cid_ & 15;                              \
            const char* p_ = (i_ >> 2) == 0 ? pkh                              \
                           : (i_ >> 2) == 1 ? pkl : pvh;                       \
            u32 d_ = sb_ + (u32)(i_ >> 2) * APL + row_ * 256 +                 \
                     (((u32)(c_ ^ (row_ & 7))) << 4);                          \
            cp16(d_, p_ + go_ + row_ * 256 + c_ * 16);                         \
        }                                                                      \
        asm volatile("cp.async.commit_group;" ::: "memory");                   \
    }

    AISSUE(0);

    const int lrow8 = lane & 7;
    const int lsel = (lane >> 3) & 1;
    const int lrow16 = lane & 15;

#define KOFF(kf_, n_) \
    ((u32)(((n_) * 8 + lrow8) * 256) + ((u32)(((kf_) * 2 + lsel) ^ lrow8) << 4))
#define VOFF(n_, kf_) \
    ((u32)(((kf_) * 16 + lrow16) * 256) + ((u32)((n_) ^ (lrow16 & 7)) << 4))

#pragma unroll 1
    for (int kt = 0; kt < TT / 64; kt++) {
        asm volatile("cp.async.wait_group 0;" ::: "memory");
        __syncthreads();
        if (kt + 1 < TT / 64) AISSUE(kt + 1);

        const u32 sb = sbase + (kt & 1) * ASTAGE;

        // ---- S = Q K^T (fp16x3), B-fragments double-buffered ----
        float s[8][4];
#pragma unroll
        for (int n = 0; n < 8; n++)
#pragma unroll
            for (int j = 0; j < 4; j++) s[n][j] = 0.f;

        {
            u32 bhf[2][2], blf[2][2];
            u32 off0 = KOFF(0, 0);
            ldsm_x2(bhf[0][0], bhf[0][1], sb + off0);
            ldsm_x2(blf[0][0], blf[0][1], sb + APL + off0);
#pragma unroll
            for (int idx = 0; idx < 64; idx++) {
                const int kf = idx >> 3, n = idx & 7;
                const int cur = idx & 1, nxt = cur ^ 1;
                if (idx < 63) {
                    const int i2 = idx + 1;
                    u32 off = KOFF(i2 >> 3, i2 & 7);
                    ldsm_x2(bhf[nxt][0], bhf[nxt][1], sb + off);
                    ldsm_x2(blf[nxt][0], blf[nxt][1], sb + APL + off);
                }
                mma_f16(s[n], Qh[kf], bhf[cur]);
                mma_f16(s[n], Ql[kf], bhf[cur]);
                mma_f16(s[n], Qh[kf], blf[cur]);
            }
        }

        // ---- online softmax (log2 domain) ----
        const float* brow = biasS + kt * 64;
        float mx0 = -1e30f, mx1 = -1e30f;
#pragma unroll
        for (int n = 0; n < 8; n++) {
            float2 bb = *(const float2*)&brow[n * 8 + 2 * fc];
            s[n][0] = fmaf(s[n][0], C, bb.x);
            s[n][1] = fmaf(s[n][1], C, bb.y);
            s[n][2] = fmaf(s[n][2], C, bb.x);
            s[n][3] = fmaf(s[n][3], C, bb.y);
            mx0 = fmaxf(mx0, fmaxf(s[n][0], s[n][1]));
            mx1 = fmaxf(mx1, fmaxf(s[n][2], s[n][3]));
        }
        mx0 = fmaxf(mx0, __shfl_xor_sync(0xffffffffu, mx0, 1));
        mx0 = fmaxf(mx0, __shfl_xor_sync(0xffffffffu, mx0, 2));
        mx1 = fmaxf(mx1, __shfl_xor_sync(0xffffffffu, mx1, 1));
        mx1 = fmaxf(mx1, __shfl_xor_sync(0xffffffffu, mx1, 2));

        float m0n = fmaxf(m0, mx0), m1n = fmaxf(m1, mx1);
        float f0 = exp2_fast(m0 - m0n), f1 = exp2_fast(m1 - m1n);
        m0 = m0n; m1 = m1n;

        float sum0 = 0.f, sum1 = 0.f;
#pragma unroll
        for (int n = 0; n < 8; n++) {
            s[n][0] = exp2_fast(s[n][0] - m0n);
            s[n][1] = exp2_fast(s[n][1] - m0n);
            s[n][2] = exp2_fast(s[n][2] - m1n);
            s[n][3] = exp2_fast(s[n][3] - m1n);
            sum0 += s[n][0] + s[n][1];
            sum1 += s[n][2] + s[n][3];
        }
        sum0 += __shfl_xor_sync(0xffffffffu, sum0, 1);
        sum0 += __shfl_xor_sync(0xffffffffu, sum0, 2);
        sum1 += __shfl_xor_sync(0xffffffffu, sum1, 1);
        sum1 += __shfl_xor_sync(0xffffffffu, sum1, 2);
        l0 = l0 * f0 + sum0;
        l1 = l1 * f1 + sum1;

#pragma unroll
        for (int n = 0; n < 16; n++) {
            o[n][0] *= f0; o[n][1] *= f0;
            o[n][2] *= f1; o[n][3] *= f1;
        }

        // pack P -> single fp16 A fragments
        u32 pa[4][4];
#pragma unroll
        for (int kf = 0; kf < 4; kf++) {
            pa[kf][0] = packf16(s[2 * kf][0], s[2 * kf][1]);
            pa[kf][1] = packf16(s[2 * kf][2], s[2 * kf][3]);
            pa[kf][2] = packf16(s[2 * kf + 1][0], s[2 * kf + 1][1]);
            pa[kf][3] = packf16(s[2 * kf + 1][2], s[2 * kf + 1][3]);
        }

        // ---- O += P V (single fp16 mma), V fragments double-buffered ----
        {
            u32 bv[2][2];
            u32 off0 = VOFF(0, 0);
            ldsm_x2_t(bv[0][0], bv[0][1], sb + 2 * APL + off0);
#pragma unroll
            for (int idx = 0; idx < 64; idx++) {
                const int n = idx >> 2, kf = idx & 3;
                const int cur = idx & 1, nxt = cur ^ 1;
                if (idx < 63) {
                    const int i2 = idx + 1;
                    u32 off = VOFF(i2 >> 2, i2 & 3);
                    ldsm_x2_t(bv[nxt][0], bv[nxt][1], sb + 2 * APL + off);
                }
                mma_f16(o[n], pa[kf], bv[cur]);
            }
        }
    }
#undef AISSUE
#undef KOFF
#undef VOFF

    // ---- normalize and store (tf32-rounded) ----
    float inv0 = 1.f / l0, inv1 = 1.f / l1;
    {
        size_t r0 = (size_t)(b * TT + qt * 128 + warp * 16 + fr) * DD + h * HDIM;
        size_t r1 = r0 + (size_t)8 * DD;
#pragma unroll
        for (int n = 0; n < 16; n++) {
            int cc = n * 8 + 2 * fc;
            *(float2*)(y + r0 + cc) = make_float2(
                __uint_as_float(f2tf32(o[n][0] * inv0)),
                __uint_as_float(f2tf32(o[n][1] * inv0)));
            *(float2*)(y + r1 + cc) = make_float2(
                __uint_as_float(f2tf32(o[n][2] * inv1)),
                __uint_as_float(f2tf32(o[n][3] * inv1)));
        }
    }
}

// ---------------------------------------------------------------------------
// Launch
// ---------------------------------------------------------------------------
extern "C" void kernel_launch(void* const* d_in, const int* in_sizes, int n_in,
                              void* d_out, int out_size) {
    const float* x     = (const float*)d_in[0];
    const int*   mask  = (const int*)d_in[1];
    const float* w_qkv = (const float*)d_in[2];
    const float* w_o   = (const float*)d_in[3];
    float* out = (float*)d_out;

    float *qkv, *yb, *xr, *wq, *wo;
    u32 *kh, *kl, *vh;
    cudaGetSymbolAddress((void**)&qkv, g_qkv);
    cudaGetSymbolAddress((void**)&yb, g_y);
    cudaGetSymbolAddress((void**)&xr, g_xr);
    cudaGetSymbolAddress((void**)&wq, g_wq);
    cudaGetSymbolAddress((void**)&wo, g_wo);
    cudaGetSymbolAddress((void**)&kh, g_kh);
    cudaGetSymbolAddress((void**)&kl, g_kl);
    cudaGetSymbolAddress((void**)&vh, g_vh);
    cudaFuncSetAttribute(gemm_nt_tf32p, cudaFuncAttributeMaxDynamicSharedMemorySize,
                         GEMM_SMEM3);
    cudaFuncSetAttribute(attn_mma, cudaFuncAttributeMaxDynamicSharedMemorySize,
                         ATTN3_SMEM);

    // Pre-round GEMM inputs to tf32
    {
        int n4x = (BB * TT * DD) / 4;
        int n4q = (3 * DD * DD) / 4;
        int n4o = (DD * DD) / 4;
        round_tf32<<<(n4x + 255) / 256, 256>>>(x, xr, n4x);
        round_tf32<<<(n4q + 255) / 256, 256>>>(w_qkv, wq, n4q);
        round_tf32<<<(n4o + 255) / 256, 256>>>(w_o, wo, n4o);
    }

    // QKV = X @ Wqkv^T, K/V sections split to fp16 planes in-epilogue
    gemm_nt_tf32p<<<dim3(3 * DD / 128, BB * TT / 128), 256, GEMM_SMEM3>>>(
        xr, wq, qkv, BB * TT, 3 * DD, DD, kh, kl, vh, 1);

    // Attention -> y (tf32-rounded)
    attn_mma<<<dim3(TT / 128, BB * HH), 256, ATTN3_SMEM>>>(
        qkv, mask, kh, kl, vh, yb);

    // out = Y @ Wo^T
    gemm_nt_tf32p<<<dim3(DD / 128, BB * TT / 128), 256, GEMM_SMEM3>>>(
        yb, wo, out, BB * TT, DD, DD, nullptr, nullptr, nullptr, 0);
}